// round 2
// baseline (speedup 1.0000x reference)
#include <cuda_runtime.h>
#include <math.h>

#define NFFT      4096
#define CIN       4
#define COUT      4
#define RANK      4
#define BATCH     32
#define NTHREADS  512
#define NPER      (NFFT / NTHREADS)   // 8 elements per thread

#ifndef M_PI
#define M_PI 3.14159265358979323846
#endif

// ---------------- device scratch (static globals; no runtime allocation) ----
__device__ float2 d_tw[NFFT];                    // exp(-2*pi*i*k/N)
__device__ float2 d_D[NFFT];                     // exp(+i*pi*k/N)
__device__ float2 d_Gf[CIN*COUT*RANK][NFFT];     // FFT(G)
__device__ float2 d_Hf[CIN*COUT*RANK][NFFT];     // FFT(D*H)
__device__ float2 d_Xf[CIN*BATCH][NFFT];         // IFFT(conj(D)*x)

// ---------------- complex helpers ----------------
__device__ __forceinline__ float2 cmul(float2 a, float2 b) {
    return make_float2(fmaf(a.x, b.x, -a.y*b.y), fmaf(a.x, b.y, a.y*b.x));
}
__device__ __forceinline__ float2 cadd(float2 a, float2 b){ return make_float2(a.x+b.x, a.y+b.y); }
__device__ __forceinline__ float2 csub(float2 a, float2 b){ return make_float2(a.x-b.x, a.y-b.y); }

// ---------------- 4096-pt radix-4 Stockham FFT in shared memory -------------
// SIGN = -1 forward, +1 inverse (unscaled). Result ends in sA (6 stages, even).
// Requires NTHREADS threads, all participating.
template<int SIGN>
__device__ void fft4096(float2* sA, float2* sB) {
    float2* src = sA;
    float2* dst = sB;
    #pragma unroll
    for (int p = 1; p <= NFFT/4; p *= 4) {
        const int tstride = (NFFT/4) / p;
        __syncthreads();
        #pragma unroll
        for (int t = threadIdx.x; t < NFFT/4; t += NTHREADS) {
            int k = t & (p - 1);
            int j = ((t - k) << 2) + k;
            float2 u0 = src[t];
            float2 u1 = src[t +   NFFT/4];
            float2 u2 = src[t +   NFFT/2];
            float2 u3 = src[t + 3*NFFT/4];
            float2 w1 = d_tw[k * tstride];
            if (SIGN > 0) w1.y = -w1.y;
            float2 w2 = cmul(w1, w1);
            float2 w3 = cmul(w2, w1);
            u1 = cmul(u1, w1);
            u2 = cmul(u2, w2);
            u3 = cmul(u3, w3);
            float2 s0 = cadd(u0, u2), dd0 = csub(u0, u2);
            float2 s1 = cadd(u1, u3), dd1 = csub(u1, u3);
            // forward: -i*dd1 ; inverse: +i*dd1
            float2 jd1 = (SIGN < 0) ? make_float2(dd1.y, -dd1.x)
                                    : make_float2(-dd1.y, dd1.x);
            dst[j]         = cadd(s0, s1);
            dst[j +     p] = cadd(dd0, jd1);
            dst[j + 2 * p] = csub(s0, s1);
            dst[j + 3 * p] = csub(dd0, jd1);
        }
        float2* tmp = src; src = dst; dst = tmp;
    }
    __syncthreads();
}

// ---------------- kernel 0: twiddle / D tables ------------------------------
__global__ void init_tw_kernel() {
    int k = blockIdx.x * blockDim.x + threadIdx.x;
    if (k < NFFT) {
        double a = -2.0 * M_PI * (double)k / (double)NFFT;
        d_tw[k] = make_float2((float)cos(a), (float)sin(a));
        double bta = M_PI * (double)k / (double)NFFT;
        d_D[k] = make_float2((float)cos(bta), (float)sin(bta));
    }
}

// ---------------- kernel 1: Gf = FFT(G), Hf = FFT(D*H) ----------------------
__global__ void __launch_bounds__(NTHREADS)
k_gh(const float* __restrict__ G, const float* __restrict__ H) {
    extern __shared__ float2 sm[];
    float2* sA = sm;
    float2* sB = sm + NFFT;
    int v = blockIdx.x;              // 0..63 -> G, 64..127 -> H
    bool isH = (v >= CIN*COUT*RANK);
    int vv = isH ? v - CIN*COUT*RANK : v;
    const float* src = isH ? H : G;

    for (int q = threadIdx.x; q < NFFT; q += NTHREADS) {
        float val = src[(size_t)vv * NFFT + q];
        if (isH) {
            float2 Dq = d_D[q];
            sA[q] = make_float2(val * Dq.x, val * Dq.y);
        } else {
            sA[q] = make_float2(val, 0.0f);
        }
    }
    fft4096<-1>(sA, sB);
    float2* dstv = isH ? d_Hf[vv] : d_Gf[vv];
    for (int q = threadIdx.x; q < NFFT; q += NTHREADS)
        dstv[q] = sA[q];
}

// ---------------- kernel 2: Xf = IFFT(conj(D)*x) ----------------------------
__global__ void __launch_bounds__(NTHREADS)
k_x(const float* __restrict__ x) {
    extern __shared__ float2 sm[];
    float2* sA = sm;
    float2* sB = sm + NFFT;
    int v = blockIdx.x;              // i*BATCH + b, 0..127
    for (int q = threadIdx.x; q < NFFT; q += NTHREADS) {
        float val = x[(size_t)v * NFFT + q];
        float2 Dq = d_D[q];
        sA[q] = make_float2(val * Dq.x, -val * Dq.y);   // conj(D)*x
    }
    fft4096<1>(sA, sB);
    const float inv = 1.0f / (float)NFFT;
    for (int q = threadIdx.x; q < NFFT; q += NTHREADS) {
        float2 t = sA[q];
        d_Xf[v][q] = make_float2(t.x * inv, t.y * inv);
    }
}

// ---------------- kernel 3: main loop over (i,s), freq-domain accumulate ----
__global__ void __launch_bounds__(NTHREADS)
k_main(float* __restrict__ out) {
    extern __shared__ float2 sm[];
    float2* sA = sm;
    float2* sB = sm + NFFT;
    const int j = blockIdx.x;        // cout index
    const int b = blockIdx.y;        // batch index

    float2 acc[NPER];
    #pragma unroll
    for (int q = 0; q < NPER; q++) acc[q] = make_float2(0.0f, 0.0f);

    for (int i = 0; i < CIN; i++) {
        const float2* __restrict__ Xf = d_Xf[i * BATCH + b];
        for (int s = 0; s < RANK; s++) {
            const int v = (i * COUT + j) * RANK + s;
            const float2* __restrict__ Hf = d_Hf[v];
            // w = Hf * Xf  (each thread fills its own slots; fft syncs first)
            #pragma unroll
            for (int q = 0; q < NPER; q++) {
                int idx = threadIdx.x + q * NTHREADS;
                sA[idx] = cmul(__ldg(&Hf[idx]), __ldg(&Xf[idx]));
            }
            fft4096<-1>(sA, sB);
            // t = D * FFT(w)
            #pragma unroll
            for (int q = 0; q < NPER; q++) {
                int idx = threadIdx.x + q * NTHREADS;
                sA[idx] = cmul(sA[idx], d_D[idx]);
            }
            fft4096<-1>(sA, sB);
            // acc += Gf * Tf   (register-resident frequency accumulator)
            const float2* __restrict__ Gf = d_Gf[v];
            #pragma unroll
            for (int q = 0; q < NPER; q++) {
                int idx = threadIdx.x + q * NTHREADS;
                acc[q] = cadd(acc[q], cmul(__ldg(&Gf[idx]), sA[idx]));
            }
        }
    }
    // out[j,b] = Re IFFT(acc) / N
    #pragma unroll
    for (int q = 0; q < NPER; q++) {
        int idx = threadIdx.x + q * NTHREADS;
        sA[idx] = acc[q];
    }
    fft4096<1>(sA, sB);
    const float inv = 1.0f / (float)NFFT;
    size_t base = ((size_t)j * BATCH + b) * NFFT;
    #pragma unroll
    for (int q = 0; q < NPER; q++) {
        int idx = threadIdx.x + q * NTHREADS;
        out[base + idx] = sA[idx].x * inv;
    }
}

// ---------------- launch ----------------------------------------------------
extern "C" void kernel_launch(void* const* d_in, const int* in_sizes, int n_in,
                              void* d_out, int out_size) {
    const float* x = (const float*)d_in[0];   // (CIN, B, N)
    const float* G = (const float*)d_in[1];   // (CIN, COUT, R, N)
    const float* H = (const float*)d_in[2];   // (CIN, COUT, R, N)
    float* out = (float*)d_out;               // (COUT, B, N) fp32

    const size_t shmem = 2 * NFFT * sizeof(float2);   // 64 KB ping-pong
    cudaFuncSetAttribute(k_gh,   cudaFuncAttributeMaxDynamicSharedMemorySize, (int)shmem);
    cudaFuncSetAttribute(k_x,    cudaFuncAttributeMaxDynamicSharedMemorySize, (int)shmem);
    cudaFuncSetAttribute(k_main, cudaFuncAttributeMaxDynamicSharedMemorySize, (int)shmem);

    init_tw_kernel<<<NFFT / 256, 256>>>();
    k_gh<<<2 * CIN * COUT * RANK, NTHREADS, shmem>>>(G, H);
    k_x<<<CIN * BATCH, NTHREADS, shmem>>>(x);
    k_main<<<dim3(COUT, BATCH), NTHREADS, shmem>>>(out);
}

// round 3
// speedup vs baseline: 2.0312x; 2.0312x over previous
#include <cuda_runtime.h>
#include <math.h>

#define NFFT   4096
#define CIN    4
#define COUT   4
#define RANK   4
#define BATCH  32
#define NT     256          // threads per CTA
#define NR     16           // radix / elements per thread
#define SMEMN  4224         // 4096 + 4096/32 padding
#define PADIDX(i) ((i) + ((i) >> 5))

#ifndef M_PI
#define M_PI 3.14159265358979323846
#endif

// ---------------- device scratch (static; no runtime allocation) ------------
__device__ float2 d_tw[NFFT];                      // exp(-2*pi*i*k/N)
__device__ float2 d_D[NFFT];                       // exp(+i*pi*k/N)
__device__ float2 d_Gf[CIN*COUT*RANK][NFFT];       // FFT(G)
__device__ float2 d_Hf[CIN*COUT*RANK][NFFT];       // FFT(D*H)
__device__ float2 d_Xf[CIN*BATCH][NFFT];           // IFFT(conj(D)*x)
__device__ float2 d_Yp[CIN][COUT*BATCH][NFFT];     // per-i partial spectra

// ---------------- complex helpers -------------------------------------------
__device__ __forceinline__ float2 cmul(float2 a, float2 b) {
    return make_float2(fmaf(a.x, b.x, -a.y*b.y), fmaf(a.x, b.y, a.y*b.x));
}
__device__ __forceinline__ float2 cadd(float2 a, float2 b){ return make_float2(a.x+b.x, a.y+b.y); }
__device__ __forceinline__ float2 csub(float2 a, float2 b){ return make_float2(a.x-b.x, a.y-b.y); }

// radix-4 butterfly in place (a,b,c,d are inputs at stride N/4 order)
template<int SIGN>
__device__ __forceinline__ void b4(float2& a, float2& b, float2& c, float2& d) {
    float2 s0 = cadd(a, c), d0 = csub(a, c);
    float2 s1 = cadd(b, d), d1 = csub(b, d);
    float2 jd1 = (SIGN < 0) ? make_float2(d1.y, -d1.x) : make_float2(-d1.y, d1.x);
    a = cadd(s0, s1);
    b = cadd(d0, jd1);
    c = csub(s0, s1);
    d = csub(d0, jd1);
}

template<int SIGN>
__device__ __forceinline__ float2 W16(float c, float s) {
    return make_float2(c, (SIGN < 0) ? -s : s);
}

// 16-pt DFT, natural order in/out, fully in registers (two radix-4 passes).
template<int SIGN>
__device__ __forceinline__ void dft16(float2 u[16]) {
    const float C1 = 0.92387953251128674f;   // cos(pi/8)
    const float S1 = 0.38268343236508978f;   // sin(pi/8)
    const float HQ = 0.70710678118654752f;   // sqrt(2)/2
    // pass 1 (p=1): groups (u[t],u[t+4],u[t+8],u[t+12]); reg u[a+4c] = v[4a+c]
    #pragma unroll
    for (int t = 0; t < 4; t++) b4<SIGN>(u[t], u[t+4], u[t+8], u[t+12]);
    // pass 2 (p=4): group t reads v[t+4c] = u[4t+c], twiddle w16^{c*t}
    float2 y[16];
    {   // t = 0 : no twiddles
        float2 e0=u[0], e1=u[1], e2=u[2], e3=u[3];
        b4<SIGN>(e0,e1,e2,e3);
        y[0]=e0; y[4]=e1; y[8]=e2; y[12]=e3;
    }
    {   // t = 1 : w^1, w^2, w^3
        float2 e0=u[4];
        float2 e1=cmul(u[5], W16<SIGN>(C1, S1));
        float2 e2=cmul(u[6], W16<SIGN>(HQ, HQ));
        float2 e3=cmul(u[7], W16<SIGN>(S1, C1));
        b4<SIGN>(e0,e1,e2,e3);
        y[1]=e0; y[5]=e1; y[9]=e2; y[13]=e3;
    }
    {   // t = 2 : w^2, w^4, w^6
        float2 e0=u[8];
        float2 e1=cmul(u[9],  W16<SIGN>(HQ, HQ));
        float2 e2=cmul(u[10], W16<SIGN>(0.f, 1.f));
        float2 e3=cmul(u[11], W16<SIGN>(-HQ, HQ));
        b4<SIGN>(e0,e1,e2,e3);
        y[2]=e0; y[6]=e1; y[10]=e2; y[14]=e3;
    }
    {   // t = 3 : w^3, w^6, w^9
        float2 e0=u[12];
        float2 e1=cmul(u[13], W16<SIGN>(S1, C1));
        float2 e2=cmul(u[14], W16<SIGN>(-HQ, HQ));
        float2 e3=cmul(u[15], W16<SIGN>(-C1, -S1));
        b4<SIGN>(e0,e1,e2,e3);
        y[3]=e0; y[7]=e1; y[11]=e2; y[15]=e3;
    }
    #pragma unroll
    for (int m = 0; m < 16; m++) u[m] = y[m];
}

// multiply u[1..15] by w1^r, chained squares (low live-register variant)
__device__ __forceinline__ void twiddle15(float2 u[16], float2 w1) {
    float2 w2 = cmul(w1, w1);
    float2 w3 = cmul(w2, w1);
    float2 w4 = cmul(w2, w2);
    u[1] = cmul(u[1], w1);
    u[2] = cmul(u[2], w2);
    u[3] = cmul(u[3], w3);
    u[4] = cmul(u[4], w4);
    float2 w5 = cmul(w4, w1);  u[5] = cmul(u[5], w5);
    float2 w6 = cmul(w4, w2);  u[6] = cmul(u[6], w6);
    float2 w7 = cmul(w4, w3);  u[7] = cmul(u[7], w7);
    float2 w8 = cmul(w4, w4);  u[8] = cmul(u[8], w8);
    u[9]  = cmul(u[9],  cmul(w8, w1));
    u[10] = cmul(u[10], cmul(w8, w2));
    u[11] = cmul(u[11], cmul(w8, w3));
    u[12] = cmul(u[12], cmul(w8, w4));
    u[13] = cmul(u[13], cmul(w8, w5));
    u[14] = cmul(u[14], cmul(w8, w6));
    u[15] = cmul(u[15], cmul(w8, w7));
}

// 4096-pt FFT, radix-16, 3 stages, 256 threads. Register in/out:
// entry : u[r] = x[t + 256 r]
// exit  : u[r] = X[t + 256 r]
// Only 2 shared round-trips. Safe to call back-to-back (no trailing sync needed).
template<int SIGN>
__device__ __forceinline__ void fftR16(float2 u[16], float2* sA, float2* sB) {
    const int t = threadIdx.x;
    // stage 1 (p=1): k=0, no twiddle
    dft16<SIGN>(u);
    #pragma unroll
    for (int r = 0; r < 16; r++) sA[PADIDX(16*t + r)] = u[r];
    __syncthreads();
    // stage 2 (p=16)
    #pragma unroll
    for (int r = 0; r < 16; r++) u[r] = sA[PADIDX(t + 256*r)];
    {
        int k = t & 15;
        float2 w1 = d_tw[k << 4];
        if (SIGN > 0) w1.y = -w1.y;
        twiddle15(u, w1);
    }
    dft16<SIGN>(u);
    #pragma unroll
    for (int r = 0; r < 16; r++)
        sB[PADIDX(((t >> 4) << 8) + (t & 15) + 16*r)] = u[r];
    __syncthreads();
    // stage 3 (p=256): output stays in registers
    #pragma unroll
    for (int r = 0; r < 16; r++) u[r] = sB[PADIDX(t + 256*r)];
    {
        float2 w1 = d_tw[t];
        if (SIGN > 0) w1.y = -w1.y;
        twiddle15(u, w1);
    }
    dft16<SIGN>(u);
}

// ---------------- kernel 0: twiddle / D tables ------------------------------
__global__ void init_tw_kernel() {
    int k = blockIdx.x * blockDim.x + threadIdx.x;
    if (k < NFFT) {
        double a = -2.0 * M_PI * (double)k / (double)NFFT;
        d_tw[k] = make_float2((float)cos(a), (float)sin(a));
        double bt = M_PI * (double)k / (double)NFFT;
        d_D[k] = make_float2((float)cos(bt), (float)sin(bt));
    }
}

// ---------------- kernel 1: precompute Gf, Hf, Xf ---------------------------
__global__ void __launch_bounds__(NT, 2)
k_pre(const float* __restrict__ x, const float* __restrict__ G,
      const float* __restrict__ H) {
    extern __shared__ float2 sm[];
    float2* sA = sm;
    float2* sB = sm + SMEMN;
    const int t = threadIdx.x;
    const int v = blockIdx.x;          // 0..63 G, 64..127 H, 128..255 x
    float2 u[16];

    if (v < CIN*COUT*RANK) {
        #pragma unroll
        for (int r = 0; r < 16; r++) {
            int idx = t + 256*r;
            u[r] = make_float2(G[(size_t)v * NFFT + idx], 0.0f);
        }
        fftR16<-1>(u, sA, sB);
        #pragma unroll
        for (int r = 0; r < 16; r++) d_Gf[v][t + 256*r] = u[r];
    } else if (v < 2*CIN*COUT*RANK) {
        int vv = v - CIN*COUT*RANK;
        #pragma unroll
        for (int r = 0; r < 16; r++) {
            int idx = t + 256*r;
            float val = H[(size_t)vv * NFFT + idx];
            float2 Dq = d_D[idx];
            u[r] = make_float2(val * Dq.x, val * Dq.y);
        }
        fftR16<-1>(u, sA, sB);
        #pragma unroll
        for (int r = 0; r < 16; r++) d_Hf[vv][t + 256*r] = u[r];
    } else {
        int vv = v - 2*CIN*COUT*RANK;  // i*BATCH + b, 0..127
        #pragma unroll
        for (int r = 0; r < 16; r++) {
            int idx = t + 256*r;
            float val = x[(size_t)vv * NFFT + idx];
            float2 Dq = d_D[idx];
            u[r] = make_float2(val * Dq.x, -val * Dq.y);     // conj(D)*x
        }
        fftR16<1>(u, sA, sB);
        const float inv = 1.0f / (float)NFFT;
        #pragma unroll
        for (int r = 0; r < 16; r++)
            d_Xf[vv][t + 256*r] = make_float2(u[r].x * inv, u[r].y * inv);
    }
}

// ---------------- kernel 2: main — one CTA per (j, b, i) --------------------
__global__ void __launch_bounds__(NT, 2)
k_main() {
    extern __shared__ float2 sm[];
    float2* sA = sm;
    float2* sB = sm + SMEMN;
    const int t = threadIdx.x;
    const int j = blockIdx.x;          // cout
    const int b = blockIdx.y;          // batch
    const int i = blockIdx.z;          // cin

    const float2* __restrict__ Xf = d_Xf[i * BATCH + b];

    float2 acc[16];
    #pragma unroll
    for (int r = 0; r < 16; r++) acc[r] = make_float2(0.0f, 0.0f);

    #pragma unroll 1
    for (int s = 0; s < RANK; s++) {
        const int v = (i * COUT + j) * RANK + s;
        const float2* __restrict__ Hf = d_Hf[v];
        const float2* __restrict__ Gf = d_Gf[v];
        float2 u[16];
        #pragma unroll
        for (int r = 0; r < 16; r++) {
            int idx = t + 256*r;
            u[r] = cmul(__ldg(&Hf[idx]), __ldg(&Xf[idx]));
        }
        fftR16<-1>(u, sA, sB);
        #pragma unroll
        for (int r = 0; r < 16; r++) u[r] = cmul(u[r], d_D[t + 256*r]);
        fftR16<-1>(u, sA, sB);
        #pragma unroll
        for (int r = 0; r < 16; r++)
            acc[r] = cadd(acc[r], cmul(__ldg(&Gf[t + 256*r]), u[r]));
    }
    float2* __restrict__ dst = d_Yp[i][j * BATCH + b];
    #pragma unroll
    for (int r = 0; r < 16; r++) dst[t + 256*r] = acc[r];
}

// ---------------- kernel 3: sum partials, final IFFT, real output -----------
__global__ void __launch_bounds__(NT, 2)
k_final(float* __restrict__ out) {
    extern __shared__ float2 sm[];
    float2* sA = sm;
    float2* sB = sm + SMEMN;
    const int t = threadIdx.x;
    const int jb = blockIdx.x;         // j*BATCH + b, 0..127

    float2 u[16];
    #pragma unroll
    for (int r = 0; r < 16; r++) {
        int idx = t + 256*r;
        float2 a0 = d_Yp[0][jb][idx];
        float2 a1 = d_Yp[1][jb][idx];
        float2 a2 = d_Yp[2][jb][idx];
        float2 a3 = d_Yp[3][jb][idx];
        u[r] = cadd(cadd(a0, a1), cadd(a2, a3));
    }
    fftR16<1>(u, sA, sB);
    const float inv = 1.0f / (float)NFFT;
    size_t base = (size_t)jb * NFFT;
    #pragma unroll
    for (int r = 0; r < 16; r++)
        out[base + t + 256*r] = u[r].x * inv;
}

// ---------------- launch ----------------------------------------------------
extern "C" void kernel_launch(void* const* d_in, const int* in_sizes, int n_in,
                              void* d_out, int out_size) {
    const float* x = (const float*)d_in[0];   // (CIN, B, N)
    const float* G = (const float*)d_in[1];   // (CIN, COUT, R, N)
    const float* H = (const float*)d_in[2];   // (CIN, COUT, R, N)
    float* out = (float*)d_out;               // (COUT, B, N) fp32

    const int shmem = 2 * SMEMN * (int)sizeof(float2);   // 67584 B
    cudaFuncSetAttribute(k_pre,   cudaFuncAttributeMaxDynamicSharedMemorySize, shmem);
    cudaFuncSetAttribute(k_main,  cudaFuncAttributeMaxDynamicSharedMemorySize, shmem);
    cudaFuncSetAttribute(k_final, cudaFuncAttributeMaxDynamicSharedMemorySize, shmem);

    init_tw_kernel<<<NFFT / 256, 256>>>();
    k_pre<<<2 * CIN * COUT * RANK + CIN * BATCH, NT, shmem>>>(x, G, H);
    k_main<<<dim3(COUT, BATCH, CIN), NT, shmem>>>();
    k_final<<<COUT * BATCH, NT, shmem>>>(out);
}

// round 4
// speedup vs baseline: 2.8047x; 1.3808x over previous
#include <cuda_runtime.h>
#include <math.h>

#define NFFT   4096
#define MH     2048            // half length
#define CIN    4
#define COUT   4
#define RANK   4
#define BATCH  32
#define LT_N   128             // threads per FFT lane
#define SMEMC  2176            // 2048 + 2048/16 padding (float2 slots)
#define P16(i) ((i) + ((i) >> 4))

#ifndef M_PI
#define M_PI 3.14159265358979323846
#endif

#define A1 ((float)(M_PI / 4096.0))   // e1 angle step: e^{i*A1*m}
#define A2 ((float)(M_PI / 2048.0))   // wB angle step: e^{-i*A2*m}
#define INV_M (1.0f / 2048.0f)

// ---------------- device scratch (static; no runtime allocation) ------------
__device__ float2 d_tw[NFFT];                       // exp(-2*pi*i*k/4096)
__device__ float2 d_Gf[CIN*COUT*RANK][MH];          // rfft(g) bins 0..2047
__device__ float  d_GfN[CIN*COUT*RANK];             // rfft(g) Nyquist bin (real)
__device__ float2 d_Hf[CIN*COUT*RANK][MH];          // folded negacyclic transform of h~
__device__ float2 d_Xf[CIN*BATCH][MH];              // folded negacyclic transform of x
__device__ float2 d_Yp[CIN][COUT*BATCH][MH];        // per-i partial spectra (half)
__device__ float  d_YpN[CIN][COUT*BATCH];           // per-i partial Nyquist

// ---------------- complex helpers -------------------------------------------
__device__ __forceinline__ float2 cmul(float2 a, float2 b) {
    return make_float2(fmaf(a.x, b.x, -a.y*b.y), fmaf(a.x, b.y, a.y*b.x));
}
__device__ __forceinline__ float2 cadd(float2 a, float2 b){ return make_float2(a.x+b.x, a.y+b.y); }
__device__ __forceinline__ float2 csub(float2 a, float2 b){ return make_float2(a.x-b.x, a.y-b.y); }
__device__ __forceinline__ float2 cconj(float2 a){ return make_float2(a.x, -a.y); }

template<int SIGN>
__device__ __forceinline__ void b4(float2& a, float2& b, float2& c, float2& d) {
    float2 s0 = cadd(a, c), d0 = csub(a, c);
    float2 s1 = cadd(b, d), d1 = csub(b, d);
    float2 jd1 = (SIGN < 0) ? make_float2(d1.y, -d1.x) : make_float2(-d1.y, d1.x);
    a = cadd(s0, s1);
    b = cadd(d0, jd1);
    c = csub(s0, s1);
    d = csub(d0, jd1);
}

template<int SIGN>
__device__ __forceinline__ float2 W16(float c, float s) {
    return make_float2(c, (SIGN < 0) ? -s : s);
}

// 16-pt DFT, natural order in/out, in registers.
template<int SIGN>
__device__ __forceinline__ void dft16(float2 u[16]) {
    const float C1 = 0.92387953251128674f;
    const float S1 = 0.38268343236508978f;
    const float HQ = 0.70710678118654752f;
    #pragma unroll
    for (int t = 0; t < 4; t++) b4<SIGN>(u[t], u[t+4], u[t+8], u[t+12]);
    float2 y[16];
    {
        float2 e0=u[0], e1=u[1], e2=u[2], e3=u[3];
        b4<SIGN>(e0,e1,e2,e3);
        y[0]=e0; y[4]=e1; y[8]=e2; y[12]=e3;
    }
    {
        float2 e0=u[4];
        float2 e1=cmul(u[5], W16<SIGN>(C1, S1));
        float2 e2=cmul(u[6], W16<SIGN>(HQ, HQ));
        float2 e3=cmul(u[7], W16<SIGN>(S1, C1));
        b4<SIGN>(e0,e1,e2,e3);
        y[1]=e0; y[5]=e1; y[9]=e2; y[13]=e3;
    }
    {
        float2 e0=u[8];
        float2 e1=cmul(u[9],  W16<SIGN>(HQ, HQ));
        float2 e2=cmul(u[10], W16<SIGN>(0.f, 1.f));
        float2 e3=cmul(u[11], W16<SIGN>(-HQ, HQ));
        b4<SIGN>(e0,e1,e2,e3);
        y[2]=e0; y[6]=e1; y[10]=e2; y[14]=e3;
    }
    {
        float2 e0=u[12];
        float2 e1=cmul(u[13], W16<SIGN>(S1, C1));
        float2 e2=cmul(u[14], W16<SIGN>(-HQ, HQ));
        float2 e3=cmul(u[15], W16<SIGN>(-C1, -S1));
        b4<SIGN>(e0,e1,e2,e3);
        y[3]=e0; y[7]=e1; y[11]=e2; y[15]=e3;
    }
    #pragma unroll
    for (int m = 0; m < 16; m++) u[m] = y[m];
}

// 8-pt DFT, natural order in/out.
template<int SIGN>
__device__ __forceinline__ void dft8(float2 u[8]) {
    const float HQ = 0.70710678118654752f;
    float2 e0=u[0], e1=u[2], e2=u[4], e3=u[6];
    float2 o0=u[1], o1=u[3], o2=u[5], o3=u[7];
    b4<SIGN>(e0,e1,e2,e3);
    b4<SIGN>(o0,o1,o2,o3);
    float2 w1 = W16<SIGN>(HQ, HQ);
    float2 w2 = W16<SIGN>(0.f, 1.f);
    float2 w3 = W16<SIGN>(-HQ, HQ);
    float2 t1 = cmul(o1, w1), t2 = cmul(o2, w2), t3 = cmul(o3, w3);
    u[0]=cadd(e0,o0); u[4]=csub(e0,o0);
    u[1]=cadd(e1,t1); u[5]=csub(e1,t1);
    u[2]=cadd(e2,t2); u[6]=csub(e2,t2);
    u[3]=cadd(e3,t3); u[7]=csub(e3,t3);
}

__device__ __forceinline__ void twiddle15(float2 u[16], float2 w1) {
    float2 w2 = cmul(w1, w1);
    float2 w3 = cmul(w2, w1);
    float2 w4 = cmul(w2, w2);
    u[1] = cmul(u[1], w1);
    u[2] = cmul(u[2], w2);
    u[3] = cmul(u[3], w3);
    u[4] = cmul(u[4], w4);
    float2 w5 = cmul(w4, w1);  u[5] = cmul(u[5], w5);
    float2 w6 = cmul(w4, w2);  u[6] = cmul(u[6], w6);
    float2 w7 = cmul(w4, w3);  u[7] = cmul(u[7], w7);
    float2 w8 = cmul(w4, w4);  u[8] = cmul(u[8], w8);
    u[9]  = cmul(u[9],  cmul(w8, w1));
    u[10] = cmul(u[10], cmul(w8, w2));
    u[11] = cmul(u[11], cmul(w8, w3));
    u[12] = cmul(u[12], cmul(w8, w4));
    u[13] = cmul(u[13], cmul(w8, w5));
    u[14] = cmul(u[14], cmul(w8, w6));
    u[15] = cmul(u[15], cmul(w8, w7));
}

__device__ __forceinline__ void twiddle7(float2 u[8], float2 w1) {
    float2 w2 = cmul(w1, w1), w3 = cmul(w2, w1), w4 = cmul(w2, w2);
    u[1] = cmul(u[1], w1); u[2] = cmul(u[2], w2); u[3] = cmul(u[3], w3);
    u[4] = cmul(u[4], w4);
    u[5] = cmul(u[5], cmul(w4, w1));
    u[6] = cmul(u[6], cmul(w4, w2));
    u[7] = cmul(u[7], cmul(w4, w3));
}

// 2048-pt FFT, radix 16*16*8, LT_N=128 threads per lane, 16 regs/thread.
// Register layout in AND out: u[r] = data[lt + 128*r].
// Leading __syncthreads guards caller's pending smem reads vs stage-1 stores.
template<int SIGN>
__device__ __forceinline__ void fft2048(float2 u[16], float2* sA, float2* sB, int lt) {
    __syncthreads();
    // stage 1: R=16, p=1 (no twiddle)
    dft16<SIGN>(u);
    #pragma unroll
    for (int c = 0; c < 16; c++) sA[P16(16*lt + c)] = u[c];
    __syncthreads();
    // stage 2: R=16, p=16
    #pragma unroll
    for (int c = 0; c < 16; c++) u[c] = sA[P16(lt + 128*c)];
    {
        int k = lt & 15;
        float2 w1 = d_tw[k << 4];          // e^{-2pi i k/256}
        if (SIGN > 0) w1.y = -w1.y;
        twiddle15(u, w1);
    }
    dft16<SIGN>(u);
    {
        int j = ((lt >> 4) << 8) + (lt & 15);
        #pragma unroll
        for (int c = 0; c < 16; c++) sB[P16(j + 16*c)] = u[c];
    }
    __syncthreads();
    // stage 3: R=8, p=256; thread handles butterflies lt and lt+128
    #pragma unroll
    for (int c = 0; c < 16; c++) u[c] = sB[P16(lt + 128*c)];
    float2 xa[8], xb[8];
    #pragma unroll
    for (int c = 0; c < 8; c++) { xa[c] = u[2*c]; xb[c] = u[2*c+1]; }
    {
        float2 wa = d_tw[2*lt];            // e^{-2pi i lt/2048}
        float2 wb = d_tw[2*lt + 256];      // e^{-2pi i (lt+128)/2048}
        if (SIGN > 0) { wa.y = -wa.y; wb.y = -wb.y; }
        twiddle7(xa, wa); twiddle7(xb, wb);
    }
    dft8<SIGN>(xa); dft8<SIGN>(xb);
    #pragma unroll
    for (int c = 0; c < 8; c++) { u[2*c] = xa[c]; u[2*c+1] = xb[c]; }
}

// ---------------- kernel 0: twiddle table -----------------------------------
__global__ void init_tw_kernel() {
    int k = blockIdx.x * blockDim.x + threadIdx.x;
    if (k < NFFT) {
        double a = -2.0 * M_PI * (double)k / (double)NFFT;
        d_tw[k] = make_float2((float)cos(a), (float)sin(a));
    }
}

// ---------------- kernel 1: precompute Gf (rfft), Hf, Xf (folded) -----------
__global__ void __launch_bounds__(LT_N)
k_pre(const float* __restrict__ x, const float* __restrict__ G,
      const float* __restrict__ H) {
    extern __shared__ float2 sm[];
    float2* sA = sm;
    float2* sB = sm + SMEMC;
    const int lt = threadIdx.x;
    const int v = blockIdx.x;            // 0..63 G, 64..127 H, 128..255 x
    float2 u[16];

    if (v < CIN*COUT*RANK) {
        // ---- G: rfft half-spectrum via even/odd packing ----
        const float2* g2 = (const float2*)(G + (size_t)v * NFFT);
        #pragma unroll
        for (int r = 0; r < 16; r++) u[r] = g2[lt + 128*r];
        fft2048<-1>(u, sA, sB, lt);
        // partner exchange + unfold
        #pragma unroll
        for (int r = 0; r < 16; r++) sA[P16(lt + 128*r)] = u[r];
        __syncthreads();
        #pragma unroll
        for (int r = 0; r < 16; r++) {
            int m = lt + 128*r;
            int pm = (MH - m) & (MH - 1);
            float2 Zp = sA[P16(pm)];
            float2 E  = make_float2(0.5f*(u[r].x + Zp.x), 0.5f*(u[r].y - Zp.y));
            float2 Od = make_float2(0.5f*(u[r].x - Zp.x), 0.5f*(u[r].y + Zp.y));
            float2 O  = make_float2(Od.y, -Od.x);          // -i * Od
            float sn, cs; __sincosf(A2 * (float)m, &sn, &cs);
            float2 wB = make_float2(cs, -sn);              // e^{-i pi m/2048}
            d_Gf[v][m] = cadd(E, cmul(wB, O));
            if (m == 0) d_GfN[v] = u[r].x - u[r].y;        // Nyquist (real)
        }
    } else if (v < 2*CIN*COUT*RANK) {
        // ---- H: folded transform of h~ = (h0, -h_{N-1}, ..., -h_1) ----
        int vv = v - CIN*COUT*RANK;
        const float* h = H + (size_t)vv * NFFT;
        #pragma unroll
        for (int r = 0; r < 16; r++) {
            int m = lt + 128*r;
            float2 bv;
            if (m == 0) {
                bv = make_float2(h[0], -h[MH]);
            } else {
                float hr = h[NFFT - m], hi = h[MH - m];
                float sn, cs; __sincosf(A1 * (float)m, &sn, &cs);
                // b = -(hr + i hi) * (cs + i sn)
                bv = make_float2(-(hr*cs - hi*sn), -(hr*sn + hi*cs));
            }
            u[r] = bv;
        }
        fft2048<-1>(u, sA, sB, lt);
        #pragma unroll
        for (int r = 0; r < 16; r++) d_Hf[vv][lt + 128*r] = u[r];
    } else {
        // ---- x: folded transform ----
        int ib = v - 2*CIN*COUT*RANK;    // 0..127
        const float* xp = x + (size_t)ib * NFFT;
        #pragma unroll
        for (int r = 0; r < 16; r++) {
            int m = lt + 128*r;
            float xr = xp[m], xi = xp[m + MH];
            float sn, cs; __sincosf(A1 * (float)m, &sn, &cs);
            u[r] = cmul(make_float2(xr, xi), make_float2(cs, sn));
        }
        fft2048<-1>(u, sA, sB, lt);
        #pragma unroll
        for (int r = 0; r < 16; r++) d_Xf[ib][lt + 128*r] = u[r];
    }
}

// ---------------- kernel 2: main — CTA (j,b,i), 2 lanes x 2 s-values --------
__global__ void __launch_bounds__(256, 2)
k_main() {
    extern __shared__ float2 sm[];
    const int t = threadIdx.x;
    const int lane = t >> 7;
    const int lt = t & 127;
    float2* sA  = sm + (size_t)lane * 2 * SMEMC;
    float2* sB  = sA + SMEMC;
    float2* sXf = sm + 4 * SMEMC;         // 2048 slots, shared by both lanes
    const int j = blockIdx.x;
    const int b = blockIdx.y;
    const int i = blockIdx.z;
    const int jb = j * BATCH + b;

    // cache X^ once per CTA
    for (int q = t; q < MH; q += 256) sXf[q] = d_Xf[i * BATCH + b][q];
    __syncthreads();

    float2 acc[16];
    #pragma unroll
    for (int r = 0; r < 16; r++) acc[r] = make_float2(0.0f, 0.0f);
    float accN = 0.0f;

    #pragma unroll 1
    for (int sp = 0; sp < 2; sp++) {
        const int s = 2*sp + lane;
        const int v = (i * COUT + j) * RANK + s;
        const float2* __restrict__ Hf = d_Hf[v];
        const float2* __restrict__ Gf = d_Gf[v];
        float2 u[16];
        // T^ = H^ * X^
        #pragma unroll
        for (int r = 0; r < 16; r++) {
            int m = lt + 128*r;
            u[r] = cmul(__ldg(&Hf[m]), sXf[m]);
        }
        // c = IFFTu(T^)
        fft2048<1>(u, sA, sB, lt);
        // unpack: t_k = Re(e1bar*c)/M, t_{k+M} = Im(...)/M   into lane smem
        float* sT = (float*)sA;
        #pragma unroll
        for (int r = 0; r < 16; r++) {
            int m = lt + 128*r;
            float sn, cs; __sincosf(A1 * (float)m, &sn, &cs);
            float2 ce = cmul(u[r], make_float2(cs, -sn));
            sT[m]      = ce.x * INV_M;
            sT[m + MH] = ce.y * INV_M;
        }
        __syncthreads();
        // repack for cyclic rfft: z_m = t_{2m} + i t_{2m+1}
        #pragma unroll
        for (int r = 0; r < 16; r++) u[r] = ((float2*)sT)[lt + 128*r];
        fft2048<-1>(u, sA, sB, lt);
        // partner exchange + Hermitian unfold, multiply Gf, accumulate
        #pragma unroll
        for (int r = 0; r < 16; r++) sA[P16(lt + 128*r)] = u[r];
        __syncthreads();
        #pragma unroll
        for (int r = 0; r < 16; r++) {
            int m = lt + 128*r;
            int pm = (MH - m) & (MH - 1);
            float2 Zp = sA[P16(pm)];
            float2 E  = make_float2(0.5f*(u[r].x + Zp.x), 0.5f*(u[r].y - Zp.y));
            float2 Od = make_float2(0.5f*(u[r].x - Zp.x), 0.5f*(u[r].y + Zp.y));
            float2 O  = make_float2(Od.y, -Od.x);
            float sn, cs; __sincosf(A2 * (float)m, &sn, &cs);
            float2 Tf = cadd(E, cmul(make_float2(cs, -sn), O));
            acc[r] = cadd(acc[r], cmul(__ldg(&Gf[m]), Tf));
            if (m == 0)
                accN = fmaf(d_GfN[v], u[r].x - u[r].y, accN);
        }
        __syncthreads();   // partner reads done before sA is reused
    }

    // combine the two lanes, store partial
    float2* sA1 = sm + 2 * SMEMC;
    float* sNy = (float*)sXf;
    if (lane == 1) {
        #pragma unroll
        for (int r = 0; r < 16; r++) sA1[P16(lt + 128*r)] = acc[r];
        if (lt == 0) sNy[0] = accN;
    }
    __syncthreads();
    if (lane == 0) {
        #pragma unroll
        for (int r = 0; r < 16; r++) {
            int m = lt + 128*r;
            d_Yp[i][jb][m] = cadd(acc[r], sA1[P16(m)]);
        }
        if (lt == 0) d_YpN[i][jb] = accN + sNy[0];
    }
}

// ---------------- kernel 3: sum partials, inverse rfft, real output ---------
__global__ void __launch_bounds__(LT_N)
k_final(float* __restrict__ out) {
    extern __shared__ float2 sm[];
    float2* sA = sm;
    float2* sB = sm + SMEMC;
    const int lt = threadIdx.x;
    const int jb = blockIdx.x;            // 0..127

    float2 u[16];
    float SN = 0.0f;
    #pragma unroll
    for (int r = 0; r < 16; r++) {
        int m = lt + 128*r;
        float2 S = cadd(cadd(d_Yp[0][jb][m], d_Yp[1][jb][m]),
                        cadd(d_Yp[2][jb][m], d_Yp[3][jb][m]));
        sA[P16(m)] = S;
        u[r] = S;
    }
    if (lt == 0)
        SN = d_YpN[0][jb] + d_YpN[1][jb] + d_YpN[2][jb] + d_YpN[3][jb];
    __syncthreads();
    #pragma unroll
    for (int r = 0; r < 16; r++) {
        int m = lt + 128*r;
        int pm = (MH - m) & (MH - 1);
        float2 P = (m == 0) ? make_float2(SN, 0.0f) : sA[P16(pm)];
        float2 E    = make_float2(0.5f*(u[r].x + P.x), 0.5f*(u[r].y - P.y));
        float2 diff = make_float2(0.5f*(u[r].x - P.x), 0.5f*(u[r].y + P.y));
        float sn, cs; __sincosf(A2 * (float)m, &sn, &cs);
        float2 O = cmul(make_float2(cs, sn), diff);        // e^{+i pi m/2048} * diff
        u[r] = make_float2(E.x - O.y, E.y + O.x);          // Z = E + iO
    }
    fft2048<1>(u, sA, sB, lt);
    float2* outp = (float2*)(out + (size_t)jb * NFFT);
    #pragma unroll
    for (int r = 0; r < 16; r++) {
        int m = lt + 128*r;
        outp[m] = make_float2(u[r].x * INV_M, u[r].y * INV_M);
    }
}

// ---------------- launch ----------------------------------------------------
extern "C" void kernel_launch(void* const* d_in, const int* in_sizes, int n_in,
                              void* d_out, int out_size) {
    const float* x = (const float*)d_in[0];   // (CIN, B, N)
    const float* G = (const float*)d_in[1];   // (CIN, COUT, R, N)
    const float* H = (const float*)d_in[2];   // (CIN, COUT, R, N)
    float* out = (float*)d_out;               // (COUT, B, N) fp32

    const int shmem_lane = 2 * SMEMC * (int)sizeof(float2);          // 34816
    const int shmem_main = (4 * SMEMC + MH) * (int)sizeof(float2);   // 86016
    cudaFuncSetAttribute(k_pre,   cudaFuncAttributeMaxDynamicSharedMemorySize, shmem_lane);
    cudaFuncSetAttribute(k_main,  cudaFuncAttributeMaxDynamicSharedMemorySize, shmem_main);
    cudaFuncSetAttribute(k_final, cudaFuncAttributeMaxDynamicSharedMemorySize, shmem_lane);

    init_tw_kernel<<<NFFT / 256, 256>>>();
    k_pre<<<2 * CIN * COUT * RANK + CIN * BATCH, LT_N, shmem_lane>>>(x, G, H);
    k_main<<<dim3(COUT, BATCH, CIN), 256, shmem_main>>>();
    k_final<<<COUT * BATCH, LT_N, shmem_lane>>>(out);
}

// round 5
// speedup vs baseline: 3.6739x; 1.3099x over previous
#include <cuda_runtime.h>
#include <math.h>
#include <string.h>

#define NFFT   4096
#define MH     2048            // half length
#define CIN    4
#define COUT   4
#define RANK   4
#define BATCH  32
#define NPART  (CIN*RANK)      // 16 partials per (j,b)
#define SMEMC  2176            // 2048 + 2048/16 padding (float2 slots)
#define P16(i) ((i) + ((i) >> 4))

#define TWO_PI 6.283185307179586476f
#define A1 ((float)(3.14159265358979323846 / 4096.0))   // e^{i*A1*m}
#define A2 ((float)(3.14159265358979323846 / 2048.0))   // e^{-i*A2*m}
#define INV_M (1.0f / 2048.0f)

// ---------------- device scratch (static; no runtime allocation) ------------
__device__ float2 d_Gf[CIN*COUT*RANK][MH];          // rfft(g) bins 0..2047
__device__ float  d_GfN[CIN*COUT*RANK];             // rfft(g) Nyquist bin (real)
__device__ float2 d_Hf[CIN*COUT*RANK][MH];          // folded negacyclic transform of h~
__device__ float2 d_Xf[CIN*BATCH][MH];              // folded negacyclic transform of x
__device__ float2 d_Yp[NPART][COUT*BATCH][MH];      // per-(i,s) partial spectra
__device__ float  d_YpN[NPART][COUT*BATCH];         // per-(i,s) partial Nyquist

// ---------------- complex helpers -------------------------------------------
__device__ __forceinline__ float2 cmul(float2 a, float2 b) {
    return make_float2(fmaf(a.x, b.x, -a.y*b.y), fmaf(a.x, b.y, a.y*b.x));
}
// packed f32x2 add/sub (sm_100+): one issue slot for both lanes
__device__ __forceinline__ float2 cadd(float2 a, float2 b) {
    unsigned long long au, bu, ru;
    memcpy(&au, &a, 8); memcpy(&bu, &b, 8);
    asm("add.rn.f32x2 %0, %1, %2;" : "=l"(ru) : "l"(au), "l"(bu));
    float2 r; memcpy(&r, &ru, 8); return r;
}
__device__ __forceinline__ float2 csub(float2 a, float2 b) {
    unsigned long long au, bu, ru;
    memcpy(&au, &a, 8); memcpy(&bu, &b, 8);
    asm("sub.rn.f32x2 %0, %1, %2;" : "=l"(ru) : "l"(au), "l"(bu));
    float2 r; memcpy(&r, &ru, 8); return r;
}

template<int SIGN>
__device__ __forceinline__ void b4(float2& a, float2& b, float2& c, float2& d) {
    float2 s0 = cadd(a, c), d0 = csub(a, c);
    float2 s1 = cadd(b, d), d1 = csub(b, d);
    a = cadd(s0, s1);
    c = csub(s0, s1);
    float2 nb, nd;
    if (SIGN < 0) {   // jd1 = (d1.y, -d1.x)
        nb = make_float2(d0.x + d1.y, d0.y - d1.x);
        nd = make_float2(d0.x - d1.y, d0.y + d1.x);
    } else {          // jd1 = (-d1.y, d1.x)
        nb = make_float2(d0.x - d1.y, d0.y + d1.x);
        nd = make_float2(d0.x + d1.y, d0.y - d1.x);
    }
    b = nb; d = nd;
}

template<int SIGN>
__device__ __forceinline__ float2 W16(float c, float s) {
    return make_float2(c, (SIGN < 0) ? -s : s);
}

// 16-pt DFT, natural order in/out, in registers.
template<int SIGN>
__device__ __forceinline__ void dft16(float2 u[16]) {
    const float C1 = 0.92387953251128674f;
    const float S1 = 0.38268343236508978f;
    const float HQ = 0.70710678118654752f;
    #pragma unroll
    for (int t = 0; t < 4; t++) b4<SIGN>(u[t], u[t+4], u[t+8], u[t+12]);
    float2 y[16];
    {
        float2 e0=u[0], e1=u[1], e2=u[2], e3=u[3];
        b4<SIGN>(e0,e1,e2,e3);
        y[0]=e0; y[4]=e1; y[8]=e2; y[12]=e3;
    }
    {
        float2 e0=u[4];
        float2 e1=cmul(u[5], W16<SIGN>(C1, S1));
        float2 e2=cmul(u[6], W16<SIGN>(HQ, HQ));
        float2 e3=cmul(u[7], W16<SIGN>(S1, C1));
        b4<SIGN>(e0,e1,e2,e3);
        y[1]=e0; y[5]=e1; y[9]=e2; y[13]=e3;
    }
    {
        float2 e0=u[8];
        float2 e1=cmul(u[9],  W16<SIGN>(HQ, HQ));
        float2 e2=cmul(u[10], W16<SIGN>(0.f, 1.f));
        float2 e3=cmul(u[11], W16<SIGN>(-HQ, HQ));
        b4<SIGN>(e0,e1,e2,e3);
        y[2]=e0; y[6]=e1; y[10]=e2; y[14]=e3;
    }
    {
        float2 e0=u[12];
        float2 e1=cmul(u[13], W16<SIGN>(S1, C1));
        float2 e2=cmul(u[14], W16<SIGN>(-HQ, HQ));
        float2 e3=cmul(u[15], W16<SIGN>(-C1, -S1));
        b4<SIGN>(e0,e1,e2,e3);
        y[3]=e0; y[7]=e1; y[11]=e2; y[15]=e3;
    }
    #pragma unroll
    for (int m = 0; m < 16; m++) u[m] = y[m];
}

// 8-pt DFT, natural order in/out.
template<int SIGN>
__device__ __forceinline__ void dft8(float2 u[8]) {
    const float HQ = 0.70710678118654752f;
    float2 e0=u[0], e1=u[2], e2=u[4], e3=u[6];
    float2 o0=u[1], o1=u[3], o2=u[5], o3=u[7];
    b4<SIGN>(e0,e1,e2,e3);
    b4<SIGN>(o0,o1,o2,o3);
    float2 t1 = cmul(o1, W16<SIGN>(HQ, HQ));
    float2 t2 = cmul(o2, W16<SIGN>(0.f, 1.f));
    float2 t3 = cmul(o3, W16<SIGN>(-HQ, HQ));
    u[0]=cadd(e0,o0); u[4]=csub(e0,o0);
    u[1]=cadd(e1,t1); u[5]=csub(e1,t1);
    u[2]=cadd(e2,t2); u[6]=csub(e2,t2);
    u[3]=cadd(e3,t3); u[7]=csub(e3,t3);
}

__device__ __forceinline__ void twiddle15(float2 u[16], float2 w1) {
    float2 w2 = cmul(w1, w1);
    float2 w3 = cmul(w2, w1);
    float2 w4 = cmul(w2, w2);
    u[1] = cmul(u[1], w1);
    u[2] = cmul(u[2], w2);
    u[3] = cmul(u[3], w3);
    u[4] = cmul(u[4], w4);
    float2 w5 = cmul(w4, w1);  u[5] = cmul(u[5], w5);
    float2 w6 = cmul(w4, w2);  u[6] = cmul(u[6], w6);
    float2 w7 = cmul(w4, w3);  u[7] = cmul(u[7], w7);
    float2 w8 = cmul(w4, w4);  u[8] = cmul(u[8], w8);
    u[9]  = cmul(u[9],  cmul(w8, w1));
    u[10] = cmul(u[10], cmul(w8, w2));
    u[11] = cmul(u[11], cmul(w8, w3));
    u[12] = cmul(u[12], cmul(w8, w4));
    u[13] = cmul(u[13], cmul(w8, w5));
    u[14] = cmul(u[14], cmul(w8, w6));
    u[15] = cmul(u[15], cmul(w8, w7));
}

__device__ __forceinline__ void twiddle7(float2 u[8], float2 w1) {
    float2 w2 = cmul(w1, w1), w3 = cmul(w2, w1), w4 = cmul(w2, w2);
    u[1] = cmul(u[1], w1); u[2] = cmul(u[2], w2); u[3] = cmul(u[3], w3);
    u[4] = cmul(u[4], w4);
    u[5] = cmul(u[5], cmul(w4, w1));
    u[6] = cmul(u[6], cmul(w4, w2));
    u[7] = cmul(u[7], cmul(w4, w3));
}

// 2048-pt FFT, radix 16*16*8, 128 threads, 16 regs/thread, SINGLE shared
// buffer (17.4 KB). Register layout in AND out: u[r] = data[lt + 128*r].
// Twiddles via __sincosf (no tables). Entry sync guards caller's pending
// smem reads; NO trailing sync (caller must sync before reusing sA).
template<int SIGN>
__device__ __forceinline__ void fft2048(float2 u[16], float2* sA, int lt) {
    __syncthreads();
    // stage 1: R=16, p=1 (no twiddle)
    dft16<SIGN>(u);
    #pragma unroll
    for (int c = 0; c < 16; c++) sA[P16(16*lt + c)] = u[c];
    __syncthreads();
    // stage 2: R=16, p=16
    #pragma unroll
    for (int c = 0; c < 16; c++) u[c] = sA[P16(lt + 128*c)];
    {
        float a = ((SIGN < 0) ? -TWO_PI : TWO_PI) * (float)(lt & 15) * (1.0f/256.0f);
        float sn, cs; __sincosf(a, &sn, &cs);
        twiddle15(u, make_float2(cs, sn));
    }
    dft16<SIGN>(u);
    __syncthreads();                 // all stage-2 loads done before stores
    {
        int j = ((lt >> 4) << 8) + (lt & 15);
        #pragma unroll
        for (int c = 0; c < 16; c++) sA[P16(j + 16*c)] = u[c];
    }
    __syncthreads();
    // stage 3: R=8, p=256; thread handles butterflies lt and lt+128
    #pragma unroll
    for (int c = 0; c < 16; c++) u[c] = sA[P16(lt + 128*c)];
    float2 xa[8], xb[8];
    #pragma unroll
    for (int c = 0; c < 8; c++) { xa[c] = u[2*c]; xb[c] = u[2*c+1]; }
    {
        float a = ((SIGN < 0) ? -TWO_PI : TWO_PI) * (float)lt * (1.0f/2048.0f);
        float sn, cs; __sincosf(a, &sn, &cs);
        float2 wa = make_float2(cs, sn);
        const float C1 = 0.92387953251128674f;
        const float S1 = 0.38268343236508978f;
        float2 wstep = make_float2(C1, (SIGN < 0) ? -S1 : S1);  // e^{∓i pi/8}
        float2 wb = cmul(wa, wstep);
        twiddle7(xa, wa); twiddle7(xb, wb);
    }
    dft8<SIGN>(xa); dft8<SIGN>(xb);
    #pragma unroll
    for (int c = 0; c < 8; c++) { u[2*c] = xa[c]; u[2*c+1] = xb[c]; }
}

// ---------------- kernel 1: precompute Gf (rfft), Hf, Xf (folded) -----------
__global__ void __launch_bounds__(128)
k_pre(const float* __restrict__ x, const float* __restrict__ G,
      const float* __restrict__ H) {
    extern __shared__ float2 sA[];
    const int lt = threadIdx.x;
    const int v = blockIdx.x;            // 0..63 G, 64..127 H, 128..255 x
    float2 u[16];

    if (v < CIN*COUT*RANK) {
        // ---- G: rfft half-spectrum via even/odd packing ----
        const float2* g2 = (const float2*)(G + (size_t)v * NFFT);
        #pragma unroll
        for (int r = 0; r < 16; r++) u[r] = g2[lt + 128*r];
        fft2048<-1>(u, sA, lt);
        __syncthreads();                 // stage-3 loads done before reuse
        #pragma unroll
        for (int r = 0; r < 16; r++) sA[P16(lt + 128*r)] = u[r];
        __syncthreads();
        #pragma unroll
        for (int r = 0; r < 16; r++) {
            int m = lt + 128*r;
            int pm = (MH - m) & (MH - 1);
            float2 Zp = sA[P16(pm)];
            float2 E  = make_float2(0.5f*(u[r].x + Zp.x), 0.5f*(u[r].y - Zp.y));
            float2 Od = make_float2(0.5f*(u[r].x - Zp.x), 0.5f*(u[r].y + Zp.y));
            float2 O  = make_float2(Od.y, -Od.x);          // -i * Od
            float sn, cs; __sincosf(A2 * (float)m, &sn, &cs);
            d_Gf[v][m] = cadd(E, cmul(make_float2(cs, -sn), O));
            if (m == 0) d_GfN[v] = u[r].x - u[r].y;        // Nyquist (real)
        }
    } else if (v < 2*CIN*COUT*RANK) {
        // ---- H: folded transform of h~ = (h0, -h_{N-1}, ..., -h_1) ----
        int vv = v - CIN*COUT*RANK;
        const float* h = H + (size_t)vv * NFFT;
        #pragma unroll
        for (int r = 0; r < 16; r++) {
            int m = lt + 128*r;
            float2 bv;
            if (m == 0) {
                bv = make_float2(h[0], -h[MH]);
            } else {
                float hr = h[NFFT - m], hi = h[MH - m];
                float sn, cs; __sincosf(A1 * (float)m, &sn, &cs);
                bv = make_float2(-(hr*cs - hi*sn), -(hr*sn + hi*cs));
            }
            u[r] = bv;
        }
        fft2048<-1>(u, sA, lt);
        #pragma unroll
        for (int r = 0; r < 16; r++) d_Hf[vv][lt + 128*r] = u[r];
    } else {
        // ---- x: folded transform ----
        int ib = v - 2*CIN*COUT*RANK;    // 0..127
        const float* xp = x + (size_t)ib * NFFT;
        #pragma unroll
        for (int r = 0; r < 16; r++) {
            int m = lt + 128*r;
            float xr = xp[m], xi = xp[m + MH];
            float sn, cs; __sincosf(A1 * (float)m, &sn, &cs);
            u[r] = cmul(make_float2(xr, xi), make_float2(cs, sn));
        }
        fft2048<-1>(u, sA, lt);
        #pragma unroll
        for (int r = 0; r < 16; r++) d_Xf[ib][lt + 128*r] = u[r];
    }
}

// ---------------- kernel 2: main — one CTA per (jb, i, s) -------------------
__global__ void __launch_bounds__(128, 6)
k_main() {
    extern __shared__ float2 sA[];
    const int lt = threadIdx.x;
    const int jb = blockIdx.x;           // j*BATCH + b
    const int p  = blockIdx.y;           // i*RANK + s
    const int j  = jb >> 5;              // BATCH = 32
    const int b  = jb & 31;
    const int i  = p >> 2;               // RANK = 4
    const int s  = p & 3;
    const int v  = (i * COUT + j) * RANK + s;

    const float2* __restrict__ Hf = d_Hf[v];
    const float2* __restrict__ Xf = d_Xf[i * BATCH + b];
    const float2* __restrict__ Gf = d_Gf[v];

    float2 u[16];
    // T^ = H^ * X^
    #pragma unroll
    for (int r = 0; r < 16; r++) {
        int m = lt + 128*r;
        u[r] = cmul(__ldg(&Hf[m]), __ldg(&Xf[m]));
    }
    // c = IFFTu(T^)
    fft2048<1>(u, sA, lt);
    // unpack: t_k = Re(e1bar*c)/M, t_{k+M} = Im(...)/M
    __syncthreads();                     // stage-3 loads done before reuse
    float* sT = (float*)sA;
    #pragma unroll
    for (int r = 0; r < 16; r++) {
        int m = lt + 128*r;
        float sn, cs; __sincosf(A1 * (float)m, &sn, &cs);
        float2 ce = cmul(u[r], make_float2(cs, -sn));
        sT[m]      = ce.x * INV_M;
        sT[m + MH] = ce.y * INV_M;
    }
    __syncthreads();
    // repack for cyclic rfft: z_m = t_{2m} + i t_{2m+1}
    #pragma unroll
    for (int r = 0; r < 16; r++) u[r] = ((float2*)sT)[lt + 128*r];
    fft2048<-1>(u, sA, lt);
    // partner exchange + Hermitian unfold, multiply Gf, store partial
    __syncthreads();
    #pragma unroll
    for (int r = 0; r < 16; r++) sA[P16(lt + 128*r)] = u[r];
    __syncthreads();
    float2* __restrict__ dst = d_Yp[p][jb];
    #pragma unroll
    for (int r = 0; r < 16; r++) {
        int m = lt + 128*r;
        int pm = (MH - m) & (MH - 1);
        float2 Zp = sA[P16(pm)];
        float2 E  = make_float2(0.5f*(u[r].x + Zp.x), 0.5f*(u[r].y - Zp.y));
        float2 Od = make_float2(0.5f*(u[r].x - Zp.x), 0.5f*(u[r].y + Zp.y));
        float2 O  = make_float2(Od.y, -Od.x);
        float sn, cs; __sincosf(A2 * (float)m, &sn, &cs);
        float2 Tf = cadd(E, cmul(make_float2(cs, -sn), O));
        dst[m] = cmul(__ldg(&Gf[m]), Tf);
        if (m == 0)
            d_YpN[p][jb] = d_GfN[v] * (u[r].x - u[r].y);
    }
}

// ---------------- kernel 3: sum partials, inverse rfft, real output ---------
__global__ void __launch_bounds__(128)
k_final(float* __restrict__ out) {
    extern __shared__ float2 sA[];
    const int lt = threadIdx.x;
    const int jb = blockIdx.x;           // 0..127

    float2 u[16];
    float SN = 0.0f;
    #pragma unroll
    for (int r = 0; r < 16; r++) {
        int m = lt + 128*r;
        float2 S = make_float2(0.0f, 0.0f);
        #pragma unroll
        for (int p = 0; p < NPART; p++) S = cadd(S, __ldg(&d_Yp[p][jb][m]));
        sA[P16(m)] = S;
        u[r] = S;
    }
    if (lt == 0) {
        #pragma unroll
        for (int p = 0; p < NPART; p++) SN += d_YpN[p][jb];
    }
    __syncthreads();
    #pragma unroll
    for (int r = 0; r < 16; r++) {
        int m = lt + 128*r;
        int pm = (MH - m) & (MH - 1);
        float2 P = (m == 0) ? make_float2(SN, 0.0f) : sA[P16(pm)];
        float2 E    = make_float2(0.5f*(u[r].x + P.x), 0.5f*(u[r].y - P.y));
        float2 diff = make_float2(0.5f*(u[r].x - P.x), 0.5f*(u[r].y + P.y));
        float sn, cs; __sincosf(A2 * (float)m, &sn, &cs);
        float2 O = cmul(make_float2(cs, sn), diff);        // e^{+i pi m/2048} * diff
        u[r] = make_float2(E.x - O.y, E.y + O.x);          // Z = E + iO
    }
    fft2048<1>(u, sA, lt);
    float2* outp = (float2*)(out + (size_t)jb * NFFT);
    #pragma unroll
    for (int r = 0; r < 16; r++) {
        int m = lt + 128*r;
        outp[m] = make_float2(u[r].x * INV_M, u[r].y * INV_M);
    }
}

// ---------------- launch ----------------------------------------------------
extern "C" void kernel_launch(void* const* d_in, const int* in_sizes, int n_in,
                              void* d_out, int out_size) {
    const float* x = (const float*)d_in[0];   // (CIN, B, N)
    const float* G = (const float*)d_in[1];   // (CIN, COUT, R, N)
    const float* H = (const float*)d_in[2];   // (CIN, COUT, R, N)
    float* out = (float*)d_out;               // (COUT, B, N) fp32

    const int shmem = SMEMC * (int)sizeof(float2);   // 17408 B
    cudaFuncSetAttribute(k_pre,   cudaFuncAttributeMaxDynamicSharedMemorySize, shmem);
    cudaFuncSetAttribute(k_main,  cudaFuncAttributeMaxDynamicSharedMemorySize, shmem);
    cudaFuncSetAttribute(k_final, cudaFuncAttributeMaxDynamicSharedMemorySize, shmem);

    k_pre<<<2 * CIN * COUT * RANK + CIN * BATCH, 128, shmem>>>(x, G, H);
    k_main<<<dim3(COUT * BATCH, NPART), 128, shmem>>>();
    k_final<<<COUT * BATCH, 128, shmem>>>(out);
}